// round 13
// baseline (speedup 1.0000x reference)
#include <cuda_runtime.h>
#include <cstdint>

// Z gate (DIM=2, S=1) on wires {0,5,11} of a 24-qubit register.
//   out[n] = (-1)^popc(n & SIGN_MASK) * x_real[n]   (N float32)
// SIGN_MASK bits 23,18,12 -> sign uniform per 4096-element block; flips at
// the midpoint of each 8192-element block (bit 12 toggles).
//
// Post R5-R12: DRAM mixed read/write (~4.5 TB/s, ~85MB/launch) is the floor;
// L2 policy hints/classes are inert. This round tunes shape for the best
// measured bench: grid 2048 (R9's best bench), 256-bit accesses (fewest
// memory instructions), default loads + evict-first stores (R9 combo).
//
// CTA = 1024 v8-chunks = 8192 floats. Thread handles 4 warp-strided chunks:
// k=0,1 in the first sign half (s), k=2,3 in the second (-s). Every warp
// access is a contiguous 1KB block.

#define SIGN_MASK ((1u << 23) | (1u << 18) | (1u << 12))
#define THREADS 256u
#define V8_PER_BLOCK 1024u   // 1024 * 8 = 8192 floats per CTA

struct f8 { float v[8]; };

__device__ __forceinline__ f8 ldg256(const float* p) {
    f8 r;
    asm("ld.global.nc.v8.b32 {%0,%1,%2,%3,%4,%5,%6,%7}, [%8];"
        : "=f"(r.v[0]), "=f"(r.v[1]), "=f"(r.v[2]), "=f"(r.v[3]),
          "=f"(r.v[4]), "=f"(r.v[5]), "=f"(r.v[6]), "=f"(r.v[7])
        : "l"(p));
    return r;
}

__device__ __forceinline__ void stg256_ef(float* p, const f8& r) {
    asm volatile("st.global.L2::evict_first.v8.b32 [%0], {%1,%2,%3,%4,%5,%6,%7,%8};"
                 :: "l"(p),
                    "f"(r.v[0]), "f"(r.v[1]), "f"(r.v[2]), "f"(r.v[3]),
                    "f"(r.v[4]), "f"(r.v[5]), "f"(r.v[6]), "f"(r.v[7])
                 : "memory");
}

__global__ void __launch_bounds__(256) z_phase_kernel(
    const float* __restrict__ xr,
    float* __restrict__ out)
{
    unsigned base = blockIdx.x * V8_PER_BLOCK;          // v8-chunk index
    float s = (__popc((base << 3) & SIGN_MASK) & 1) ? -1.0f : 1.0f;
    float t = -s;                                       // bit-12 flip at half

    unsigned c0 = (base + 0u * THREADS + threadIdx.x) << 3;  // float offsets
    unsigned c1 = (base + 1u * THREADS + threadIdx.x) << 3;
    unsigned c2 = (base + 2u * THREADS + threadIdx.x) << 3;
    unsigned c3 = (base + 3u * THREADS + threadIdx.x) << 3;

    f8 a = ldg256(xr + c0);
    f8 b = ldg256(xr + c1);
    f8 c = ldg256(xr + c2);
    f8 d = ldg256(xr + c3);

    #pragma unroll
    for (int k = 0; k < 8; k++) {
        a.v[k] *= s; b.v[k] *= s;   // first 4096-element half
        c.v[k] *= t; d.v[k] *= t;   // second half: sign flipped
    }

    stg256_ef(out + c0, a);
    stg256_ef(out + c1, b);
    stg256_ef(out + c2, c);
    stg256_ef(out + c3, d);
}

extern "C" void kernel_launch(void* const* d_in, const int* in_sizes, int n_in,
                              void* d_out, int out_size)
{
    const float* xr = (const float*)d_in[0];
    float* out = (float*)d_out;

    const unsigned n_v8 = (1u << 24) / 8u;             // 2,097,152 chunks
    const unsigned blocks = n_v8 / V8_PER_BLOCK;       // 2048

    z_phase_kernel<<<blocks, THREADS>>>(xr, out);
}

// round 14
// speedup vs baseline: 1.1199x; 1.1199x over previous
#include <cuda_runtime.h>
#include <cstdint>

// Z gate (DIM=2, S=1) on wires {0,5,11} of a 24-qubit register.
//   out[n] = (-1)^popc(n & SIGN_MASK) * x_real[n]   (N float32)
// SIGN_MASK bits 23,18,12 -> sign uniform over each 4096-element tile.
//
// PERSISTENT grid-stride kernel: exactly 148 SMs x 8 CTAs = 1184 CTAs, each
// looping over 4096-float tiles (grid stride). No wave transitions, no ragged
// final wave; loads of tile i+1 overlap stores of tile i inside the loop.
// Memory ops: 256-bit ld.global.nc + evict-first 256-bit stores (the combo
// with the best measured bench). Every warp access = contiguous 1KB block.

#define SIGN_MASK ((1u << 23) | (1u << 18) | (1u << 12))
#define THREADS   256u
#define N_TILES   4096u           // (1<<24) / 4096 elements per tile
#define GRID      1184u           // 148 SMs * 8 resident CTAs

struct f8 { float v[8]; };

__device__ __forceinline__ f8 ldg256(const float* p) {
    f8 r;
    asm("ld.global.nc.v8.b32 {%0,%1,%2,%3,%4,%5,%6,%7}, [%8];"
        : "=f"(r.v[0]), "=f"(r.v[1]), "=f"(r.v[2]), "=f"(r.v[3]),
          "=f"(r.v[4]), "=f"(r.v[5]), "=f"(r.v[6]), "=f"(r.v[7])
        : "l"(p));
    return r;
}

__device__ __forceinline__ void stg256_ef(float* p, const f8& r) {
    asm volatile("st.global.L2::evict_first.v8.b32 [%0], {%1,%2,%3,%4,%5,%6,%7,%8};"
                 :: "l"(p),
                    "f"(r.v[0]), "f"(r.v[1]), "f"(r.v[2]), "f"(r.v[3]),
                    "f"(r.v[4]), "f"(r.v[5]), "f"(r.v[6]), "f"(r.v[7])
                 : "memory");
}

__global__ void __launch_bounds__(256) z_phase_kernel(
    const float* __restrict__ xr,
    float* __restrict__ out)
{
    // Per-thread base offsets within a tile: two warp-strided 256-bit chunks.
    unsigned o0 = threadIdx.x << 3;                 // floats 0..2047 region
    unsigned o1 = (THREADS + threadIdx.x) << 3;     // floats 2048..4095 region

    for (unsigned tile = blockIdx.x; tile < N_TILES; tile += GRID) {
        unsigned base = tile << 12;                 // tile * 4096 floats
        // Sign uniform over the tile; only bits >=12 matter.
        float s = (__popc(base & SIGN_MASK) & 1) ? -1.0f : 1.0f;

        const float* src = xr + base;
        float*       dst = out + base;

        f8 a = ldg256(src + o0);
        f8 b = ldg256(src + o1);

        #pragma unroll
        for (int k = 0; k < 8; k++) { a.v[k] *= s; b.v[k] *= s; }

        stg256_ef(dst + o0, a);
        stg256_ef(dst + o1, b);
    }
}

extern "C" void kernel_launch(void* const* d_in, const int* in_sizes, int n_in,
                              void* d_out, int out_size)
{
    const float* xr = (const float*)d_in[0];
    float* out = (float*)d_out;

    z_phase_kernel<<<GRID, THREADS>>>(xr, out);
}